// round 1
// baseline (speedup 1.0000x reference)
#include <cuda_runtime.h>
#include <cstdint>

// SVD predict: per batch row b with (uid, iid):
//   pred[b]  = clip(gm + bu[uid] + bi[iid] + dot(pu[uid], qi[iid]), 1, 5)
//   feat[b]  = concat(pu[uid], qi[iid])   (128 floats)
//
// Inputs (metadata order):
//   d_in[0] user_item  int32  [131072, 2]
//   d_in[1] pu         f32    [1000000, 64]
//   d_in[2] qi         f32    [500000, 64]
//   d_in[3] bu         f32    [1000000]
//   d_in[4] bi         f32    [500000]
//   d_in[5] global_mean f32   [1]
// Output: float32, size 131072 + 131072*128 = 131072*129
//   layout: predict first, then features row-major.

#define BATCH     131072
#define NF        64

__global__ __launch_bounds__(256)
void svd_predict_kernel(const int2* __restrict__ ui,
                        const float* __restrict__ pu,
                        const float* __restrict__ qi,
                        const float* __restrict__ bu,
                        const float* __restrict__ bi,
                        const float* __restrict__ gm,
                        float* __restrict__ out_pred,
                        float* __restrict__ out_feat)
{
    const int warp = (blockIdx.x * blockDim.x + threadIdx.x) >> 5;
    const int lane = threadIdx.x & 31;
    if (warp >= BATCH) return;

    const int2 ids = __ldg(&ui[warp]);          // x = uid, y = iid
    const float2* __restrict__ prow =
        reinterpret_cast<const float2*>(pu + (size_t)ids.x * NF);
    const float2* __restrict__ qrow =
        reinterpret_cast<const float2*>(qi + (size_t)ids.y * NF);

    // Warp reads 64 floats (256B) contiguously from each table: fully coalesced.
    const float2 p = __ldg(&prow[lane]);
    const float2 q = __ldg(&qrow[lane]);

    float dot = p.x * q.x + p.y * q.y;
    #pragma unroll
    for (int off = 16; off; off >>= 1)
        dot += __shfl_xor_sync(0xFFFFFFFFu, dot, off);

    // Coalesced 256B feature stores: [p | q] per row.
    float2* __restrict__ frow =
        reinterpret_cast<float2*>(out_feat + (size_t)warp * (2 * NF));
    frow[lane]      = p;
    frow[lane + 32] = q;

    if (lane == 0) {
        float pr = gm[0] + __ldg(&bu[ids.x]) + __ldg(&bi[ids.y]) + dot;
        pr = fminf(fmaxf(pr, 1.0f), 5.0f);
        out_pred[warp] = pr;
    }
}

extern "C" void kernel_launch(void* const* d_in, const int* in_sizes, int n_in,
                              void* d_out, int out_size)
{
    const int2*  ui = (const int2*) d_in[0];
    const float* pu = (const float*)d_in[1];
    const float* qi = (const float*)d_in[2];
    const float* bu = (const float*)d_in[3];
    const float* bi = (const float*)d_in[4];
    const float* gm = (const float*)d_in[5];

    float* out_pred = (float*)d_out;            // [BATCH]
    float* out_feat = out_pred + BATCH;         // [BATCH, 128]

    const int threads = 256;                    // 8 warps/block
    const int blocks  = (BATCH * 32) / threads; // 16384
    svd_predict_kernel<<<blocks, threads>>>(ui, pu, qi, bu, bi, gm,
                                            out_pred, out_feat);
}

// round 2
// speedup vs baseline: 1.5863x; 1.5863x over previous
#include <cuda_runtime.h>
#include <cstdint>

// SVD predict, 4 rows per warp, float4 gathers.
//
// Inputs (metadata order):
//   d_in[0] user_item  int32  [131072, 2]
//   d_in[1] pu         f32    [1000000, 64]
//   d_in[2] qi         f32    [500000, 64]
//   d_in[3] bu         f32    [1000000]
//   d_in[4] bi         f32    [500000]
//   d_in[5] global_mean f32   [1]
// Output: float32 [131072 predict] ++ [131072 x 128 features]

#define BATCH 131072
#define NF    64
#define ROWS_PER_WARP 4

__global__ __launch_bounds__(256)
void svd_predict_kernel(const int2* __restrict__ ui,
                        const float4* __restrict__ pu4,   // [N_USERS][16]
                        const float4* __restrict__ qi4,   // [N_ITEMS][16]
                        const float* __restrict__ bu,
                        const float* __restrict__ bi,
                        const float* __restrict__ gm,
                        float* __restrict__ out_pred,
                        float4* __restrict__ out_feat4)   // [BATCH][32]
{
    const int warp = (blockIdx.x * blockDim.x + threadIdx.x) >> 5;
    const int lane = threadIdx.x & 31;
    const int half = lane >> 4;      // 0 or 1
    const int g    = lane & 15;      // lane within half-warp

    // This warp's 4 rows; this half-warp's 2 rows.
    const int r0 = warp * ROWS_PER_WARP + half * 2;
    const int r1 = r0 + 1;

    const int2 id0 = __ldg(&ui[r0]);
    const int2 id1 = __ldg(&ui[r1]);

    // 4 independent 16B gathers per thread -> 64B in flight.
    const float4 a0 = __ldg(pu4 + (size_t)id0.x * 16 + g);
    const float4 b0 = __ldg(qi4 + (size_t)id0.y * 16 + g);
    const float4 a1 = __ldg(pu4 + (size_t)id1.x * 16 + g);
    const float4 b1 = __ldg(qi4 + (size_t)id1.y * 16 + g);

    float d0 = a0.x * b0.x + a0.y * b0.y + a0.z * b0.z + a0.w * b0.w;
    float d1 = a1.x * b1.x + a1.y * b1.y + a1.z * b1.z + a1.w * b1.w;

    // Reduce within each half-warp (offsets < 16 stay inside the half).
    #pragma unroll
    for (int off = 8; off; off >>= 1) {
        d0 += __shfl_xor_sync(0xFFFFFFFFu, d0, off);
        d1 += __shfl_xor_sync(0xFFFFFFFFu, d1, off);
    }

    // Streaming feature stores: [p | q] per row, 512B/row, full lines.
    float4* f0 = out_feat4 + (size_t)r0 * 32;
    float4* f1 = out_feat4 + (size_t)r1 * 32;
    __stcs(f0 + g,      a0);
    __stcs(f0 + g + 16, b0);
    __stcs(f1 + g,      a1);
    __stcs(f1 + g + 16, b1);

    if (g == 0) {
        const float base = __ldg(gm);
        float p0 = base + __ldg(&bu[id0.x]) + __ldg(&bi[id0.y]) + d0;
        float p1 = base + __ldg(&bu[id1.x]) + __ldg(&bi[id1.y]) + d1;
        out_pred[r0] = fminf(fmaxf(p0, 1.0f), 5.0f);
        out_pred[r1] = fminf(fmaxf(p1, 1.0f), 5.0f);
    }
}

extern "C" void kernel_launch(void* const* d_in, const int* in_sizes, int n_in,
                              void* d_out, int out_size)
{
    const int2*   ui  = (const int2*)  d_in[0];
    const float4* pu4 = (const float4*)d_in[1];
    const float4* qi4 = (const float4*)d_in[2];
    const float*  bu  = (const float*) d_in[3];
    const float*  bi  = (const float*) d_in[4];
    const float*  gm  = (const float*) d_in[5];

    float*  out_pred  = (float*)d_out;                 // [BATCH]
    float4* out_feat4 = (float4*)(out_pred + BATCH);   // [BATCH][32] float4

    const int threads = 256;                                  // 8 warps
    const int warps   = BATCH / ROWS_PER_WARP;                // 32768
    const int blocks  = warps / (threads / 32);               // 4096
    svd_predict_kernel<<<blocks, threads>>>(ui, pu4, qi4, bu, bi, gm,
                                            out_pred, out_feat4);
}